// round 8
// baseline (speedup 1.0000x reference)
#include <cuda_runtime.h>

#define HID     30
#define SEQLEN  784
#define NCLS    10
#define B_MAX   16384
#define WSTRIDE 16

typedef unsigned long long u64;

// transposed inputs: g_xT[t*B + row]
__device__ float g_xT[(size_t)SEQLEN * B_MAX];

// ---- packed f32x2 helpers ----
__device__ __forceinline__ u64 dup2(float v) {
    u64 r; asm("mov.b64 %0, {%1,%1};" : "=l"(r) : "f"(v)); return r;
}
__device__ __forceinline__ u64 pk2(float lo, float hi) {
    u64 r; asm("mov.b64 %0, {%1,%2};" : "=l"(r) : "f"(lo), "f"(hi)); return r;
}
__device__ __forceinline__ float2 up2(u64 v) {
    float2 f; asm("mov.b64 {%0,%1}, %2;" : "=f"(f.x), "=f"(f.y) : "l"(v)); return f;
}
__device__ __forceinline__ u64 fma2(u64 a, u64 b, u64 c) {
    u64 d; asm("fma.rn.f32x2 %0, %1, %2, %3;" : "=l"(d) : "l"(a), "l"(b), "l"(c)); return d;
}
__device__ __forceinline__ u64 mul2(u64 a, u64 b) {
    u64 d; asm("mul.rn.f32x2 %0, %1, %2;" : "=l"(d) : "l"(a), "l"(b)); return d;
}

// modReLU: sign(z) * relu(|z| + b)
__device__ __forceinline__ float mrelu(float z, float b) {
    float t = fabsf(z) + b;
    float r = fmaxf(t, 0.0f);
    unsigned u = __float_as_uint(r) | (__float_as_uint(z) & 0x80000000u);
    return __uint_as_float(u);
}

// ---- tiled transpose: inputs[B][SEQ] -> g_xT[SEQ][B] ----
__global__ void transpose_kernel(const float* __restrict__ in, int B) {
    __shared__ float tile[32][33];
    int rb = blockIdx.x * 32;
    int tb = blockIdx.y * 32;
    int tx = threadIdx.x, ty = threadIdx.y;
#pragma unroll
    for (int i = 0; i < 4; i++) {
        int row = rb + ty + i * 8, t = tb + tx;
        tile[ty + i * 8][tx] = (t < SEQLEN) ? in[(size_t)row * SEQLEN + t] : 0.0f;
    }
    __syncthreads();
#pragma unroll
    for (int i = 0; i < 4; i++) {
        int t = tb + ty + i * 8, row = rb + tx;
        if (t < SEQLEN) g_xT[(size_t)t * B + row] = tile[tx][ty + i * 8];
    }
}

// 2 batch rows per thread: each weight-row LDS feeds FMAs for BOTH rows.
__global__ __launch_bounds__(32, 1)
void rnn_modrelu_r2(const float* __restrict__ W_ih,
                    const float* __restrict__ W_hh,
                    const float* __restrict__ b_mod,
                    const float* __restrict__ W_lin,
                    const float* __restrict__ b_lin,
                    float* __restrict__ out, int B)
{
    // sW[k*WSTRIDE + p] = (W_hh[2p][k], W_hh[2p+1][k]) -- j-pair packed, k-major
    __shared__ __align__(16) u64 sW[HID * WSTRIDE];
    __shared__ float2 sBm2[15];
    __shared__ float sWlin[NCLS * HID];
    __shared__ float sblin[NCLS];
    __shared__ float sWih[HID];

    const int tid = threadIdx.x;
    for (int i = tid; i < HID * 15; i += 32) {
        int k = i / 15, p = i % 15;
        sW[k * WSTRIDE + p] = pk2(W_hh[(2 * p) * HID + k], W_hh[(2 * p + 1) * HID + k]);
    }
    for (int i = tid; i < 15; i += 32) sBm2[i] = make_float2(b_mod[2 * i], b_mod[2 * i + 1]);
    for (int i = tid; i < NCLS * HID; i += 32) sWlin[i] = W_lin[i];
    for (int i = tid; i < HID; i += 32) sWih[i] = W_ih[i];
    for (int i = tid; i < NCLS; i += 32) sblin[i] = b_lin[i];
    __syncthreads();

    const int half = B >> 1;
    const int gid = blockIdx.x * 32 + tid;
    if (gid >= half) return;
    const int rowA = gid;
    const int rowB = gid + half;

    u64 wih2[15];
#pragma unroll
    for (int p = 0; p < 15; p++) wih2[p] = pk2(sWih[2 * p], sWih[2 * p + 1]);

    float hA[HID], hB[HID];
#pragma unroll
    for (int j = 0; j < HID; j++) { hA[j] = 0.0f; hB[j] = 0.0f; }

    const float* xpA = g_xT + rowA;   // coalesced across lanes
    const float* xpB = g_xT + rowB;
    float xA = xpA[0], xB = xpB[0];
    xpA += B; xpB += B;

    for (int t = 0; t < SEQLEN; ++t) {
        float xnA = 0.0f, xnB = 0.0f;
        if (t + 1 < SEQLEN) { xnA = *xpA; xnB = *xpB; }   // coalesced prefetch
        xpA += B; xpB += B;

        u64 xdA = dup2(xA), xdB = dup2(xB);
        u64 zA[15], zB[15];
#pragma unroll
        for (int p = 0; p < 15; p++) {
            zA[p] = mul2(xdA, wih2[p]);
            zB[p] = mul2(xdB, wih2[p]);
        }

#pragma unroll
        for (int k = 0; k < HID; k++) {
            u64 hdA = dup2(hA[k]);
            u64 hdB = dup2(hB[k]);
            const ulonglong2* wr2 = (const ulonglong2*)&sW[k * WSTRIDE];
#pragma unroll
            for (int q = 0; q < 7; q++) {           // one LDS.128 feeds 4 FMAs
                ulonglong2 w = wr2[q];
                zA[2 * q]     = fma2(hdA, w.x, zA[2 * q]);
                zB[2 * q]     = fma2(hdB, w.x, zB[2 * q]);
                zA[2 * q + 1] = fma2(hdA, w.y, zA[2 * q + 1]);
                zB[2 * q + 1] = fma2(hdB, w.y, zB[2 * q + 1]);
            }
            u64 wl = sW[k * WSTRIDE + 14];          // LDS.64 feeds 2 FMAs
            zA[14] = fma2(hdA, wl, zA[14]);
            zB[14] = fma2(hdB, wl, zB[14]);
        }

#pragma unroll
        for (int p = 0; p < 15; p++) {
            float2 bmp = sBm2[p];                   // uniform LDS.64 per pair
            float2 za = up2(zA[p]);
            float2 zb = up2(zB[p]);
            hA[2 * p]     = mrelu(za.x, bmp.x);
            hA[2 * p + 1] = mrelu(za.y, bmp.y);
            hB[2 * p]     = mrelu(zb.x, bmp.x);
            hB[2 * p + 1] = mrelu(zb.y, bmp.y);
        }
        xA = xnA; xB = xnB;
    }

    float* oA = out + (size_t)rowA * NCLS;
    float* oB = out + (size_t)rowB * NCLS;
#pragma unroll
    for (int c = 0; c < NCLS; c++) {
        float accA = sblin[c];
        float accB = sblin[c];
#pragma unroll
        for (int j = 0; j < HID; j++) {
            float w = sWlin[c * HID + j];
            accA = fmaf(hA[j], w, accA);
            accB = fmaf(hB[j], w, accB);
        }
        oA[c] = accA;
        oB[c] = accB;
    }
}

extern "C" void kernel_launch(void* const* d_in, const int* in_sizes, int n_in,
                              void* d_out, int out_size)
{
    const float* inputs = (const float*)d_in[0];
    const float* W_ih   = (const float*)d_in[1];
    const float* W_hh   = (const float*)d_in[2];
    const float* b_mod  = (const float*)d_in[3];
    const float* W_lin  = (const float*)d_in[4];
    const float* b_lin  = (const float*)d_in[5];
    float* out = (float*)d_out;

    const int B = in_sizes[0] / SEQLEN;

    // 1) transpose inputs -> g_xT[SEQ][B] (coalesced per-step x loads)
    dim3 tb(32, 8);
    dim3 tg(B / 32, (SEQLEN + 31) / 32);
    transpose_kernel<<<tg, tb>>>(inputs, B);

    // 2) main scan: 2 rows/thread, 32-thread blocks spread across SMs
    const int half = B >> 1;
    const int blocks = (half + 31) / 32;
    rnn_modrelu_r2<<<blocks, 32>>>(W_ih, W_hh, b_mod, W_lin, b_lin, out, B);
}

// round 11
// speedup vs baseline: 9.3238x; 9.3238x over previous
#include <cuda_runtime.h>

#define HID     30
#define SEQLEN  784
#define NCLS    10
#define B_MAX   16384
#define WSTRIDE 16
#define NROWS   31      // 30 W_hh rows + row 30 = W_ih

typedef unsigned long long u64;

// transposed inputs: g_xT[t*B + row]
__device__ float g_xT[(size_t)SEQLEN * B_MAX];

// ---- packed f32x2 helpers ----
__device__ __forceinline__ u64 dup2(float v) {
    u64 r; asm("mov.b64 %0, {%1,%1};" : "=l"(r) : "f"(v)); return r;
}
__device__ __forceinline__ u64 pk2(float lo, float hi) {
    u64 r; asm("mov.b64 %0, {%1,%2};" : "=l"(r) : "f"(lo), "f"(hi)); return r;
}
__device__ __forceinline__ float2 up2(u64 v) {
    float2 f; asm("mov.b64 {%0,%1}, %2;" : "=f"(f.x), "=f"(f.y) : "l"(v)); return f;
}
__device__ __forceinline__ u64 fma2(u64 a, u64 b, u64 c) {
    u64 d; asm("fma.rn.f32x2 %0, %1, %2, %3;" : "=l"(d) : "l"(a), "l"(b), "l"(c)); return d;
}
__device__ __forceinline__ u64 mul2(u64 a, u64 b) {
    u64 d; asm("mul.rn.f32x2 %0, %1, %2;" : "=l"(d) : "l"(a), "l"(b)); return d;
}

// modReLU: sign(z) * relu(|z| + b)
__device__ __forceinline__ float mrelu(float z, float b) {
    float t = fabsf(z) + b;
    float r = fmaxf(t, 0.0f);
    unsigned u = __float_as_uint(r) | (__float_as_uint(z) & 0x80000000u);
    return __uint_as_float(u);
}

// One packed weight row (15 u64 = 30 floats): 7x LDS.128 + 1x LDS.64
struct WRow {
    ulonglong2 a0, a1, a2, a3, a4, a5, a6;
    u64 last;
};
__device__ __forceinline__ WRow ldrow(const u64* base) {
    WRow r;
    const ulonglong2* w2 = (const ulonglong2*)base;
    r.a0 = w2[0]; r.a1 = w2[1]; r.a2 = w2[2]; r.a3 = w2[3];
    r.a4 = w2[4]; r.a5 = w2[5]; r.a6 = w2[6];
    r.last = base[14];
    return r;
}
__device__ __forceinline__ void mulrow(u64* z, u64 xd, const WRow& w) {
    z[0]  = mul2(xd, w.a0.x);  z[1]  = mul2(xd, w.a0.y);
    z[2]  = mul2(xd, w.a1.x);  z[3]  = mul2(xd, w.a1.y);
    z[4]  = mul2(xd, w.a2.x);  z[5]  = mul2(xd, w.a2.y);
    z[6]  = mul2(xd, w.a3.x);  z[7]  = mul2(xd, w.a3.y);
    z[8]  = mul2(xd, w.a4.x);  z[9]  = mul2(xd, w.a4.y);
    z[10] = mul2(xd, w.a5.x);  z[11] = mul2(xd, w.a5.y);
    z[12] = mul2(xd, w.a6.x);  z[13] = mul2(xd, w.a6.y);
    z[14] = mul2(xd, w.last);
}
__device__ __forceinline__ void accum(u64* z, u64 hd, const WRow& w) {
    z[0]  = fma2(hd, w.a0.x, z[0]);   z[1]  = fma2(hd, w.a0.y, z[1]);
    z[2]  = fma2(hd, w.a1.x, z[2]);   z[3]  = fma2(hd, w.a1.y, z[3]);
    z[4]  = fma2(hd, w.a2.x, z[4]);   z[5]  = fma2(hd, w.a2.y, z[5]);
    z[6]  = fma2(hd, w.a3.x, z[6]);   z[7]  = fma2(hd, w.a3.y, z[7]);
    z[8]  = fma2(hd, w.a4.x, z[8]);   z[9]  = fma2(hd, w.a4.y, z[9]);
    z[10] = fma2(hd, w.a5.x, z[10]);  z[11] = fma2(hd, w.a5.y, z[11]);
    z[12] = fma2(hd, w.a6.x, z[12]);  z[13] = fma2(hd, w.a6.y, z[13]);
    z[14] = fma2(hd, w.last, z[14]);
}

// ---- tiled transpose: inputs[B][SEQ] -> g_xT[SEQ][B] ----
__global__ void transpose_kernel(const float* __restrict__ in, int B) {
    __shared__ float tile[32][33];
    int rb = blockIdx.x * 32;
    int tb = blockIdx.y * 32;
    int tx = threadIdx.x, ty = threadIdx.y;
#pragma unroll
    for (int i = 0; i < 4; i++) {
        int row = rb + ty + i * 8, t = tb + tx;
        tile[ty + i * 8][tx] = (t < SEQLEN) ? in[(size_t)row * SEQLEN + t] : 0.0f;
    }
    __syncthreads();
#pragma unroll
    for (int i = 0; i < 4; i++) {
        int t = tb + ty + i * 8, row = rb + tx;
        if (t < SEQLEN) g_xT[(size_t)t * B + row] = tile[tx][ty + i * 8];
    }
}

__global__ __launch_bounds__(128, 1)
void rnn_modrelu_pipe2(const float* __restrict__ W_ih,
                       const float* __restrict__ W_hh,
                       const float* __restrict__ b_mod,
                       const float* __restrict__ W_lin,
                       const float* __restrict__ b_lin,
                       float* __restrict__ out, int B)
{
    // sW rows 0..29: sW[k*16+p] = (W_hh[2p][k], W_hh[2p+1][k])
    // sW row 30:     (W_ih[2p], W_ih[2p+1])
    __shared__ __align__(16) u64 sW[NROWS * WSTRIDE];
    __shared__ float2 sBm2[15];
    __shared__ float sWlin[NCLS * HID];
    __shared__ float sblin[NCLS];

    const int tid = threadIdx.x;
    for (int i = tid; i < NROWS * 15; i += 128) {
        int k = i / 15, p = i % 15;
        u64 v;
        if (k < HID) v = pk2(W_hh[(2 * p) * HID + k], W_hh[(2 * p + 1) * HID + k]);
        else         v = pk2(W_ih[2 * p], W_ih[2 * p + 1]);
        sW[k * WSTRIDE + p] = v;
    }
    for (int i = tid; i < 15; i += 128) sBm2[i] = make_float2(b_mod[2 * i], b_mod[2 * i + 1]);
    for (int i = tid; i < NCLS * HID; i += 128) sWlin[i] = W_lin[i];
    for (int i = tid; i < NCLS; i += 128) sblin[i] = b_lin[i];
    __syncthreads();

    const int row = blockIdx.x * blockDim.x + tid;
    if (row >= B) return;

    float h[HID];
#pragma unroll
    for (int j = 0; j < HID; j++) h[j] = 0.0f;

    const float* xp = g_xT + row;          // coalesced across lanes
    float x = xp[0];
    xp += B;

    WRow cur = ldrow(&sW[HID * WSTRIDE]);  // warm: row 30 = W_ih

    for (int t = 0; t < SEQLEN; ++t) {
        float xn = (t + 1 < SEQLEN) ? __ldg(xp) : 0.0f;   // coalesced prefetch
        xp += B;

        u64 xd = dup2(x);
        // prefetch row 0 while the x-projection multiplies issue
        WRow nxt = ldrow(&sW[0]);
        u64 z[15];
        mulrow(z, xd, cur);                // z = x * W_ih (row 30)
        cur = nxt;

        // rotating single-buffer k-loop: loads of row k+1 overlap FMAs of row k;
        // at k=29 the prefetch wraps to row 30 (W_ih) for step t+1.
#pragma unroll
        for (int k = 0; k < HID; k++) {
            int knext = (k + 1 < HID) ? (k + 1) : HID;     // HID -> row 30
            WRow n = ldrow(&sW[knext * WSTRIDE]);
            accum(z, dup2(h[k]), cur);
            cur = n;
        }

#pragma unroll
        for (int p = 0; p < 15; p++) {
            float2 bmp = sBm2[p];
            float2 zz = up2(z[p]);
            h[2 * p]     = mrelu(zz.x, bmp.x);
            h[2 * p + 1] = mrelu(zz.y, bmp.y);
        }
        x = xn;
    }

    float* orow = out + (size_t)row * NCLS;
#pragma unroll
    for (int c = 0; c < NCLS; c++) {
        float acc = sblin[c];
#pragma unroll
        for (int j = 0; j < HID; j++) acc = fmaf(h[j], sWlin[c * HID + j], acc);
        orow[c] = acc;
    }
}

extern "C" void kernel_launch(void* const* d_in, const int* in_sizes, int n_in,
                              void* d_out, int out_size)
{
    const float* inputs = (const float*)d_in[0];
    const float* W_ih   = (const float*)d_in[1];
    const float* W_hh   = (const float*)d_in[2];
    const float* b_mod  = (const float*)d_in[3];
    const float* W_lin  = (const float*)d_in[4];
    const float* b_lin  = (const float*)d_in[5];
    float* out = (float*)d_out;

    const int B = in_sizes[0] / SEQLEN;

    // 1) transpose inputs -> g_xT[SEQ][B] (coalesced per-step x loads)
    dim3 tb(32, 8);
    dim3 tg(B / 32, (SEQLEN + 31) / 32);
    transpose_kernel<<<tg, tb>>>(inputs, B);

    // 2) main scan: 1 row/thread, pipelined weight stream
    const int threads = 128;
    const int blocks = (B + threads - 1) / threads;
    rnn_modrelu_pipe2<<<blocks, threads>>>(W_ih, W_hh, b_mod, W_lin, b_lin, out, B);
}